// round 16
// baseline (speedup 1.0000x reference)
#include <cuda_runtime.h>
#include <cuda_fp16.h>
#include <cstdint>
#include <math.h>

#define DIM     256
#define HEADS   8
#define HDIM    32
#define GW      64
#define HW      56
#define NPIX    3136            // 56*56
#define BATCH   16
#define NTOK    (BATCH * NPIX)  // 50176
#define HIDDEN  1024
#define LN_EPS  1e-6f
#define BN_EPS  1e-3f
#define L2_EPS  1e-12f
#define SCALE_Q 0.17677669529663689f  // 32^-0.5
#define NSPLIT  14                     // 3136 = 14 * 224

// ---------------- scratch (static device globals; no cudaMalloc) -------------
__device__ __align__(16) float  d_dwconv   [NTOK * DIM];
__device__ __align__(16) __half d_norm1h   [NTOK * DIM];
__device__ __align__(16) __half d_qTh      [BATCH * HEADS * HDIM * NPIX]; // [b][h][d][n]
__device__ __align__(16) __half d_kTh      [BATCH * HEADS * HDIM * NPIX];
__device__ __align__(16) __half d_vh       [NTOK * DIM];
__device__ __align__(16) float  d_attn_part[NSPLIT * BATCH * HEADS * HDIM * HDIM];
__device__ __align__(16) __half d_wbTh     [BATCH * DIM * DIM];   // [b][c][h*32+d]
__device__ __align__(16) __half d_mergedh  [NTOK * DIM];
__device__ __align__(16) __half d_h1h      [NTOK * HIDDEN];
__device__ __align__(16) __half d_qkvTh    [768 * 256];
__device__ __align__(16) __half d_fc1T     [1024 * 256];
__device__ __align__(16) __half d_fc2T     [256 * 1024];

// ---------------- PTX helpers -------------------------------------------------
__device__ __forceinline__ void cp_async16_s(uint32_t saddr, const void* gptr) {
    asm volatile("cp.async.cg.shared.global [%0], [%1], 16;\n" :: "r"(saddr), "l"(gptr));
}
__device__ __forceinline__ void cp_commit() { asm volatile("cp.async.commit_group;\n"); }

__device__ __forceinline__ void ldsm_x4(uint32_t r[4], uint32_t addr) {
    asm volatile("ldmatrix.sync.aligned.m8n8.x4.shared.b16 {%0,%1,%2,%3}, [%4];"
        : "=r"(r[0]), "=r"(r[1]), "=r"(r[2]), "=r"(r[3]) : "r"(addr));
}
__device__ __forceinline__ void mma_f16(float c[4], const uint32_t a[4],
                                        uint32_t b0, uint32_t b1) {
    asm volatile(
        "mma.sync.aligned.m16n8k16.row.col.f32.f16.f16.f32 "
        "{%0,%1,%2,%3}, {%4,%5,%6,%7}, {%8,%9}, {%0,%1,%2,%3};"
        : "+f"(c[0]), "+f"(c[1]), "+f"(c[2]), "+f"(c[3])
        : "r"(a[0]), "r"(a[1]), "r"(a[2]), "r"(a[3]), "r"(b0), "r"(b1));
}

// ------- kernel 0: transpose one weight -> fp16 [N, K] (3 separate launches) --
__global__ void __launch_bounds__(256) transpose1_kernel(
    const float* __restrict__ src, __half* __restrict__ dst, int R, int C)
{
    int x0 = blockIdx.x * 32, y0 = blockIdx.y * 32;
    if (x0 >= C || y0 >= R) return;

    __shared__ float t[32][33];
    int tx = threadIdx.x & 31, ty = threadIdx.x >> 5;
    #pragma unroll
    for (int i = ty; i < 32; i += 8)
        t[i][tx] = src[(size_t)(y0 + i) * C + x0 + tx];
    __syncthreads();
    #pragma unroll
    for (int i = ty; i < 32; i += 8)
        dst[(size_t)(x0 + i) * R + y0 + tx] = __float2half(t[tx][i]);
}

// ---- kernel 1: dwconv3x3 + group cumsum + LayerNorm, warp-per-pixel ---------
// v3: block = 8-pixel strip along ww (56 % 8 == 0); 3x10x192 halo staged in smem
// (zero-filled at image edges -> padding handled unconditionally, fma(0,w)=+0).
__global__ void __launch_bounds__(256) dwln_kernel(
    const float* __restrict__ x, const float* __restrict__ dwk,
    const float* __restrict__ dwb, const float* __restrict__ g,
    const float* __restrict__ be)
{
    const int lane = threadIdx.x & 31;
    const int wrp  = threadIdx.x >> 5;        // pixel within strip, 0..7
    const int pix0 = blockIdx.x * 8;
    const int b   = pix0 / NPIX;
    const int p0  = pix0 - b * NPIX;
    const int hh  = p0 / HW, ww0 = p0 - hh * HW;   // ww0 multiple of 8
    const int pix = pix0 + wrp;
    const int c   = lane * 8;

    __shared__ float sH[3][10][192];          // rows hh-1..+1, cols ww0-1..+8, ch 64..255

    // cooperative halo load: 1440 float4, zero-filled outside the image
    for (int i = threadIdx.x; i < 1440; i += 256) {
        int f4   = i % 48;                    // float4 within 192 channels
        int cell = i / 48;                    // 0..29
        int cin  = cell % 10, r = cell / 10;
        int hy = hh + r - 1;
        int wx = ww0 + cin - 1;
        float4 v = make_float4(0.f, 0.f, 0.f, 0.f);
        if ((unsigned)hy < (unsigned)HW && (unsigned)wx < (unsigned)HW)
            v = *(const float4*)&x[((size_t)(b * HW + hy) * HW + wx) * DIM + GW + f4 * 4];
        *(float4*)&sH[r][cin][f4 * 4] = v;
    }
    __syncthreads();

    float val[8];
    if (lane < 8) {
        float4 a0 = *(const float4*)&x[(size_t)pix * DIM + c];
        float4 a1 = *(const float4*)&x[(size_t)pix * DIM + c + 4];
        val[0]=a0.x; val[1]=a0.y; val[2]=a0.z; val[3]=a0.w;
        val[4]=a1.x; val[5]=a1.y; val[6]=a1.z; val[7]=a1.w;
    } else {
        const int cc = c - GW;                // 0..184
        float4 b0 = *(const float4*)&dwb[cc];
        float4 b1 = *(const float4*)&dwb[cc + 4];
        val[0]=b0.x; val[1]=b0.y; val[2]=b0.z; val[3]=b0.w;
        val[4]=b1.x; val[5]=b1.y; val[6]=b1.z; val[7]=b1.w;
        #pragma unroll
        for (int ky = 0; ky < 3; ky++) {
            #pragma unroll
            for (int kx = 0; kx < 3; kx++) {
                const float* sp = &sH[ky][wrp + kx][cc];
                const float* wp = &dwk[(ky * 3 + kx) * 192 + cc];
                float4 x0 = *(const float4*)sp, x1 = *(const float4*)(sp + 4);
                float4 w0 = *(const float4*)wp, w1 = *(const float4*)(wp + 4);
                val[0] += x0.x * w0.x; val[1] += x0.y * w0.y;
                val[2] += x0.z * w0.z; val[3] += x0.w * w0.w;
                val[4] += x1.x * w1.x; val[5] += x1.y * w1.y;
                val[6] += x1.z * w1.z; val[7] += x1.w * w1.w;
            }
        }
    }

    {
        const int s0 = 8 + (lane & 7);
        const int gi = (lane >> 3) - 1;
        #pragma unroll
        for (int i = 0; i < 8; i++) {
            float k0 = __shfl_sync(0xffffffffu, val[i], s0);
            float k1 = __shfl_sync(0xffffffffu, val[i], s0 + 8);
            float k2 = __shfl_sync(0xffffffffu, val[i], s0 + 16);
            if (lane >= 8) {
                float s = k0;
                if (gi >= 1) s += k1;
                if (gi >= 2) s += k2;
                val[i] = s;
            }
        }
    }

    float sum = 0.f;
    #pragma unroll
    for (int i = 0; i < 8; i++) sum += val[i];
    #pragma unroll
    for (int o = 16; o; o >>= 1) sum += __shfl_xor_sync(0xffffffffu, sum, o);
    float mean = sum * (1.0f / 256.0f);

    float ss = 0.f;
    #pragma unroll
    for (int i = 0; i < 8; i++) { float d = val[i] - mean; ss += d * d; }
    #pragma unroll
    for (int o = 16; o; o >>= 1) ss += __shfl_xor_sync(0xffffffffu, ss, o);
    float rstd = rsqrtf(ss * (1.0f / 256.0f) + LN_EPS);

    float4 g0 = *(const float4*)&g[c],  g1 = *(const float4*)&g[c + 4];
    float4 e0 = *(const float4*)&be[c], e1 = *(const float4*)&be[c + 4];
    *(float4*)&d_dwconv[(size_t)pix * DIM + c]     = make_float4(val[0], val[1], val[2], val[3]);
    *(float4*)&d_dwconv[(size_t)pix * DIM + c + 4] = make_float4(val[4], val[5], val[6], val[7]);

    float n[8];
    n[0]=(val[0]-mean)*rstd*g0.x+e0.x; n[1]=(val[1]-mean)*rstd*g0.y+e0.y;
    n[2]=(val[2]-mean)*rstd*g0.z+e0.z; n[3]=(val[3]-mean)*rstd*g0.w+e0.w;
    n[4]=(val[4]-mean)*rstd*g1.x+e1.x; n[5]=(val[5]-mean)*rstd*g1.y+e1.y;
    n[6]=(val[6]-mean)*rstd*g1.z+e1.z; n[7]=(val[7]-mean)*rstd*g1.w+e1.w;
    __half2 h0 = __floats2half2_rn(n[0], n[1]);
    __half2 h1 = __floats2half2_rn(n[2], n[3]);
    __half2 h2 = __floats2half2_rn(n[4], n[5]);
    __half2 h3 = __floats2half2_rn(n[6], n[7]);
    uint4 u;
    u.x = *(uint32_t*)&h0; u.y = *(uint32_t*)&h1;
    u.z = *(uint32_t*)&h2; u.w = *(uint32_t*)&h3;
    *(uint4*)&d_norm1h[(size_t)pix * DIM + c] = u;
}

// -------- fp16 GEMM v2: BK=64 halves (128B rows), 3-stage single-barrier ------
// MODE 1: BN( +bias +add1 fp32 ) -> half (proj, PERBATCH)
// MODE 2: gelu(+bias) -> half (fc1)     MODE 3: +bias +add1 -> float (fc2)
// MODE 4: qkv: per-head l2norm; qTh/kTh fp16 transposed (smem-staged), vh dense
#define HG_BOFF  49152
#define HG_SMEM  98304

template<int KDIM, int MODE, bool PERBATCH>
__global__ void __launch_bounds__(256, 2)
hgemm(const __half* __restrict__ A,
      const __half* __restrict__ Bt,
      void* __restrict__ Cv, int ldc, int m_off,
      const float* __restrict__ bias, const float* __restrict__ add1,
      const float* __restrict__ bn_g, const float* __restrict__ bn_b,
      const float* __restrict__ bn_m, const float* __restrict__ bn_v)
{
    extern __shared__ char smem[];
    const uint32_t sb = (uint32_t)__cvta_generic_to_shared(smem);
    const int tid  = threadIdx.x;
    const int lane = tid & 31;
    const int w    = tid >> 5;
    const int wm   = w >> 2;
    const int wn   = w & 3;

    int m0, mrows;
    if (PERBATCH) {
        int batch = blockIdx.y / 25;
        int bt    = blockIdx.y % 25;
        m0 = batch * NPIX + bt * 128;
        mrows = min(128, NPIX - bt * 128);
    } else {
        m0 = m_off + blockIdx.y * 128; mrows = 128;
    }
    const int n0 = blockIdx.x * 128;
    const __half* Bp = PERBATCH ? (Bt + (size_t)(blockIdx.y / 25) * 65536) : Bt;

    float acc[4][4][4];
    #pragma unroll
    for (int mi = 0; mi < 4; mi++)
        #pragma unroll
        for (int ni = 0; ni < 4; ni++)
            #pragma unroll
            for (int q = 0; q < 4; q++) acc[mi][ni][q] = 0.f;

    auto load_stage = [&](int st) {
        int slot = st % 3;
        int k0 = st * 64;                 // halves
        #pragma unroll
        for (int i = 0; i < 4; i++) {
            int lin = tid + 256 * i;      // 0..1023
            int r = lin >> 3, ch = lin & 7;
            int rg = m0 + (r < mrows ? r : mrows - 1);
            cp_async16_s(sb + slot * 16384 + r * 128 + ((ch ^ (r & 7)) << 4),
                         A + (size_t)rg * KDIM + k0 + ch * 8);
        }
        #pragma unroll
        for (int i = 0; i < 4; i++) {
            int lin = tid + 256 * i;
            int r = lin >> 3, ch = lin & 7;
            cp_async16_s(sb + HG_BOFF + slot * 16384 + r * 128 + ((ch ^ (r & 7)) << 4),
                         Bp + (size_t)(n0 + r) * KDIM + k0 + ch * 8);
        }
        cp_commit();
    };

    const int KT = KDIM / 64;
    load_stage(0); load_stage(1);

    const int sx    = lane & 7;
    const int arow  = lane & 15;
    const int akoff = lane >> 4;
    const int brow  = ((lane >> 4) << 3) + (lane & 7);
    const int bkoff = (lane >> 3) & 1;

    for (int s = 0; s < KT; s++) {
        int slot = s % 3;
        if (s < KT - 1) asm volatile("cp.async.wait_group 1;\n" ::: "memory");
        else            asm volatile("cp.async.wait_group 0;\n" ::: "memory");
        __syncthreads();
        if (s + 2 < KT) load_stage(s + 2);

        uint32_t aBase = sb + slot * 16384 + (wm * 64) * 128;
        uint32_t bBase = sb + HG_BOFF + slot * 16384 + (wn * 32) * 128;

        #pragma unroll
        for (int ks = 0; ks < 4; ks++) {
            uint32_t a[4][4];
            #pragma unroll
            for (int mi = 0; mi < 4; mi++)
                ldsm_x4(a[mi], aBase + (mi * 16 + arow) * 128
                               + (((2 * ks + akoff) ^ sx) << 4));
            uint32_t bf[2][4];
            #pragma unroll
            for (int nj = 0; nj < 2; nj++)
                ldsm_x4(bf[nj], bBase + (nj * 16 + brow) * 128
                                + (((2 * ks + bkoff) ^ sx) << 4));
            #pragma unroll
            for (int mi = 0; mi < 4; mi++)
                #pragma unroll
                for (int ni = 0; ni < 4; ni++)
                    mma_f16(acc[mi][ni], a[mi],
                            bf[ni >> 1][(ni & 1) * 2], bf[ni >> 1][(ni & 1) * 2 + 1]);
        }
    }

    // ---- MODE 4 q/k path: l2norm + smem-staged transposed fp16 store ----
    if (MODE == 4 && n0 < 512) {
        float* sT = (float*)smem;             // [col 128][row 128], stride 132
        __syncthreads();
        #pragma unroll
        for (int mi = 0; mi < 4; mi++) {
            #pragma unroll
            for (int h = 0; h < 2; h++) {
                float ss = 0.f;
                #pragma unroll
                for (int ni = 0; ni < 4; ni++) {
                    float v0 = acc[mi][ni][2 * h], v1 = acc[mi][ni][2 * h + 1];
                    ss += v0 * v0 + v1 * v1;
                }
                ss += __shfl_xor_sync(0xffffffffu, ss, 1);
                ss += __shfl_xor_sync(0xffffffffu, ss, 2);
                float sc = rsqrtf(fmaxf(ss, L2_EPS));
                if (n0 < 256) sc *= SCALE_Q;

                int rowl = wm * 64 + mi * 16 + (lane >> 2) + h * 8;
                #pragma unroll
                for (int ni = 0; ni < 4; ni++) {
                    int dl = wn * 32 + ni * 8 + (lane & 3) * 2;
                    sT[dl * 132 + rowl]       = acc[mi][ni][2 * h] * sc;
                    sT[(dl + 1) * 132 + rowl] = acc[mi][ni][2 * h + 1] * sc;
                }
            }
        }
        __syncthreads();
        __half* dstT = (n0 < 256) ? d_qTh : d_kTh;
        #pragma unroll
        for (int i = 0; i < 8; i++) {
            int idx = tid + i * 256;          // 0..2047
            int cl  = idx >> 4;               // 0..127
            int row = (idx & 15) * 8;         // 0..120
            int grow = m0 + row;
            int bb = grow / NPIX;
            int n  = grow - bb * NPIX;        // 8-run never straddles batch (3136%8==0)
            int gcol = n0 + cl;
            int head = (gcol & 255) >> 5;
            int d    = gcol & 31;
            float4 v4a = *(float4*)&sT[cl * 132 + row];
            float4 v4b = *(float4*)&sT[cl * 132 + row + 4];
            __half2 p0 = __floats2half2_rn(v4a.x, v4a.y);
            __half2 p1 = __floats2half2_rn(v4a.z, v4a.w);
            __half2 p2 = __floats2half2_rn(v4b.x, v4b.y);
            __half2 p3 = __floats2half2_rn(v4b.z, v4b.w);
            uint4 u;
            u.x = *(uint32_t*)&p0; u.y = *(uint32_t*)&p1;
            u.z = *(uint32_t*)&p2; u.w = *(uint32_t*)&p3;
            *(uint4*)&dstT[((size_t)(bb * 8 + head) * 32 + d) * NPIX + n] = u;
        }
        return;
    }

    // ---- epilogue ----
    #pragma unroll
    for (int mi = 0; mi < 4; mi++) {
        #pragma unroll
        for (int h = 0; h < 2; h++) {
            int lr = wm * 64 + mi * 16 + (lane >> 2) + h * 8;
            if (PERBATCH && lr >= mrows) continue;
            size_t grow = (size_t)(m0 + lr);
            #pragma unroll
            for (int ni = 0; ni < 4; ni++) {
                float v0 = acc[mi][ni][2 * h], v1 = acc[mi][ni][2 * h + 1];
                if (MODE == 4) {
                    // v block (n0 >= 512): fp16 dense store, ldc = 256
                    int gc = (n0 - 512) + wn * 32 + ni * 8 + (lane & 3) * 2;
                    *(__half2*)((__half*)Cv + grow * ldc + gc) = __floats2half2_rn(v0, v1);
                    continue;
                }
                int gc = n0 + wn * 32 + ni * 8 + (lane & 3) * 2;
                if (MODE == 1) {
                    float2 ad = *(const float2*)&add1[grow * 256 + gc];
                    v0 += bias[gc]     + ad.x;
                    v1 += bias[gc + 1] + ad.y;
                    v0 = (v0 - bn_m[gc    ]) * rsqrtf(bn_v[gc    ] + BN_EPS) * bn_g[gc    ] + bn_b[gc    ];
                    v1 = (v1 - bn_m[gc + 1]) * rsqrtf(bn_v[gc + 1] + BN_EPS) * bn_g[gc + 1] + bn_b[gc + 1];
                    *(__half2*)((__half*)Cv + grow * ldc + gc) = __floats2half2_rn(v0, v1);
                } else if (MODE == 2) {
                    v0 += bias[gc];   v1 += bias[gc + 1];
                    v0 = 0.5f * v0 * (1.0f + erff(v0 * 0.70710678118654752f));
                    v1 = 0.5f * v1 * (1.0f + erff(v1 * 0.70710678118654752f));
                    *(__half2*)((__half*)Cv + grow * ldc + gc) = __floats2half2_rn(v0, v1);
                } else {
                    float2 ad = *(const float2*)&add1[grow * 256 + gc];
                    v0 += bias[gc]     + ad.x;
                    v1 += bias[gc + 1] + ad.y;
                    *(float2*)&((float*)Cv)[grow * ldc + gc] = make_float2(v0, v1);
                }
            }
        }
    }
}

// ------- attn split-K (fp16 mma): per (b,h,split) partial 32x32 q^T k --------
#define AS_STAGE 5120
#define AS_SMEM  15360

__global__ void __launch_bounds__(256) attn_split_kernel()
{
    extern __shared__ char smem[];
    const uint32_t sb = (uint32_t)__cvta_generic_to_shared(smem);
    const int bh = blockIdx.x;
    const int split = blockIdx.y;
    const int tid = threadIdx.x, lane = tid & 31, w = tid >> 5;
    const int wm = w >> 2, wn = w & 3;

    const __half* qT = d_qTh + (size_t)bh * 32 * NPIX + split * 224;
    const __half* kT = d_kTh + (size_t)bh * 32 * NPIX + split * 224;

    float c[4] = {0.f, 0.f, 0.f, 0.f};

    auto load_stage = [&](int st) {
        int slot = st % 3;
        int k0 = st * 32;                     // halves
        int op = tid >> 7;                    // 0 = q, 1 = k
        int rr = (tid >> 2) & 31;
        int ch = tid & 3;
        const __half* src = (op ? kT : qT) + (size_t)rr * NPIX + k0 + ch * 8;
        cp_async16_s(sb + slot * AS_STAGE + op * 2560 + rr * 80 + ch * 16, src);
        cp_commit();
    };

    const int KT = 7;                         // 224 / 32
    load_stage(0); load_stage(1);

    const int nj   = wn >> 1;
    const int nsel = (wn & 1) * 2;

    for (int s = 0; s < KT; s++) {
        int slot = s % 3;
        if (s < KT - 1) asm volatile("cp.async.wait_group 1;\n" ::: "memory");
        else            asm volatile("cp.async.wait_group 0;\n" ::: "memory");
        __syncthreads();
        if (s + 2 < KT) load_stage(s + 2);

        uint32_t aBase = sb + slot * AS_STAGE + (wm * 16) * 80;
        uint32_t bBase = sb + slot * AS_STAGE + 2560;
        #pragma unroll
        for (int ks = 0; ks < 2; ks++) {
            const int kc = ks * 2;
            uint32_t a[4], bf[4];
            ldsm_x4(a, aBase + (lane & 15) * 80 + (kc + (lane >> 4)) * 16);
            ldsm_x4(bf, bBase + (nj * 16 + ((lane >> 4) << 3) + (lane & 7)) * 80
                        + (kc + ((lane >> 3) & 1)) * 16);
            mma_f16(c, a, bf[nsel], bf[nsel + 1]);
        }
    }

    float* dst = d_attn_part + ((size_t)split * 128 + bh) * 1024;
    int row = wm * 16 + (lane >> 2);
    int col = wn * 8 + (lane & 3) * 2;
    dst[row * 32 + col]           = c[0];
    dst[row * 32 + col + 1]       = c[1];
    dst[(row + 8) * 32 + col]     = c[2];
    dst[(row + 8) * 32 + col + 1] = c[3];
}

// ------- attn finalize + softmax + wbT^h = (blockdiag attn @ proj_w)^T -------
__global__ void __launch_bounds__(1024) attn_wb_kernel(const float* __restrict__ proj_w)
{
    int bh = blockIdx.x;
    int b = bh >> 3, h = bh & 7;
    int tid = threadIdx.x;
    int e = tid & 31, d = tid >> 5;

    __shared__ float sA[32][33];
    __shared__ float sW[32][256];

    float acc = 0.f;
    #pragma unroll
    for (int s = 0; s < NSPLIT; s++)
        acc += d_attn_part[((size_t)s * 128 + bh) * 1024 + d * 32 + e];

    float m = acc;
    #pragma unroll
    for (int o = 16; o; o >>= 1) m = fmaxf(m, __shfl_xor_sync(0xffffffffu, m, o));
    float ex = expf(acc - m);
    float sum = ex;
    #pragma unroll
    for (int o = 16; o; o >>= 1) sum += __shfl_xor_sync(0xffffffffu, sum, o);
    sA[d][e] = ex / sum;

    #pragma unroll
    for (int idx = tid; idx < 8192; idx += 1024)
        sW[idx >> 8][idx & 255] = proj_w[(h * 32 + (idx >> 8)) * 256 + (idx & 255)];
    __syncthreads();

    #pragma unroll
    for (int idx = tid; idx < 8192; idx += 1024) {
        int d2 = idx & 31, c = idx >> 5;
        float s = 0.f;
        #pragma unroll
        for (int ee = 0; ee < 32; ee++) s += sA[d2][ee] * sW[ee][c];
        d_wbTh[(size_t)b * 65536 + c * 256 + h * 32 + d2] = __float2half(s);
    }
}

// ---------------- launch ------------------------------------------------------
extern "C" void kernel_launch(void* const* d_in, const int* in_sizes, int n_in,
                              void* d_out, int out_size)
{
    const float* x        = (const float*)d_in[0];
    const float* dw_kernel= (const float*)d_in[1];
    const float* dw_bias  = (const float*)d_in[2];
    const float* ln_gamma = (const float*)d_in[3];
    const float* ln_beta  = (const float*)d_in[4];
    const float* qkv_w    = (const float*)d_in[5];
    const float* proj_w   = (const float*)d_in[6];
    const float* proj_b   = (const float*)d_in[7];
    const float* bn_gamma = (const float*)d_in[8];
    const float* bn_beta  = (const float*)d_in[9];
    const float* bn_mean  = (const float*)d_in[10];
    const float* bn_var   = (const float*)d_in[11];
    const float* fc1_w    = (const float*)d_in[12];
    const float* fc1_b    = (const float*)d_in[13];
    const float* fc2_w    = (const float*)d_in[14];
    const float* fc2_b    = (const float*)d_in[15];
    float* out = (float*)d_out;

    float  *p_dwconv;
    __half *p_norm1h, *p_vh, *p_wbTh, *p_mergedh, *p_h1h, *p_qkvTh, *p_fc1T, *p_fc2T;
    cudaGetSymbolAddress((void**)&p_dwconv,  d_dwconv);
    cudaGetSymbolAddress((void**)&p_norm1h,  d_norm1h);
    cudaGetSymbolAddress((void**)&p_vh,      d_vh);
    cudaGetSymbolAddress((void**)&p_wbTh,    d_wbTh);
    cudaGetSymbolAddress((void**)&p_mergedh, d_mergedh);
    cudaGetSymbolAddress((void**)&p_h1h,     d_h1h);
    cudaGetSymbolAddress((void**)&p_qkvTh,   d_qkvTh);
    cudaGetSymbolAddress((void**)&p_fc1T,    d_fc1T);
    cudaGetSymbolAddress((void**)&p_fc2T,    d_fc2T);

    cudaFuncSetAttribute(hgemm<256, 4, false>,
                         cudaFuncAttributeMaxDynamicSharedMemorySize, HG_SMEM);
    cudaFuncSetAttribute(hgemm<256, 1, true>,
                         cudaFuncAttributeMaxDynamicSharedMemorySize, HG_SMEM);
    cudaFuncSetAttribute(hgemm<256, 2, false>,
                         cudaFuncAttributeMaxDynamicSharedMemorySize, HG_SMEM);
    cudaFuncSetAttribute(hgemm<1024, 3, false>,
                         cudaFuncAttributeMaxDynamicSharedMemorySize, HG_SMEM);

    // 1-3) transpose weights, one launch each (puts dwln in ncu slot 4)
    transpose1_kernel<<<dim3(24, 8), 256>>>(qkv_w, p_qkvTh, 256, 768);
    transpose1_kernel<<<dim3(32, 8), 256>>>(fc1_w, p_fc1T, 256, 1024);
    transpose1_kernel<<<dim3(8, 32), 256>>>(fc2_w, p_fc2T, 1024, 256);

    // 4) dwconv + cumsum + LN (smem halo strip)      <- profiled launch
    dwln_kernel<<<NTOK / 8, 256>>>(x, dw_kernel, dw_bias, ln_gamma, ln_beta);

    // 5) qkv GEMM (fp16, BK=64), single launch; qTh/kTh/vh fp16 outputs
    hgemm<256, 4, false><<<dim3(6, 392), 256, HG_SMEM>>>(
        p_norm1h, p_qkvTh, p_vh, 256, 0,
        nullptr, nullptr, nullptr, nullptr, nullptr, nullptr);

    // 6) attn partials (fp16 mma, split-K x14)
    attn_split_kernel<<<dim3(BATCH * HEADS, NSPLIT), 256, AS_SMEM>>>();

    // 7) softmax + wbT (fp16)
    attn_wb_kernel<<<BATCH * HEADS, 1024>>>(proj_w);

    // 8) merged = BN( v @ W_b + proj_b + dwconv ) -> fp16   (fp16 GEMM, per-batch)
    hgemm<256, 1, true><<<dim3(2, BATCH * 25), 256, HG_SMEM>>>(
        p_vh, p_wbTh, p_mergedh, 256, 0,
        proj_b, p_dwconv, bn_gamma, bn_beta, bn_mean, bn_var);

    // 9) h1 = gelu(merged @ fc1_w + fc1_b) -> fp16
    hgemm<256, 2, false><<<dim3(8, NTOK / 128), 256, HG_SMEM>>>(
        p_mergedh, p_fc1T, p_h1h, 1024, 0,
        fc1_b, nullptr, nullptr, nullptr, nullptr, nullptr);

    // 10) out = h1 @ fc2_w + fc2_b + x -> fp32
    hgemm<1024, 3, false><<<dim3(2, NTOK / 128), 256, HG_SMEM>>>(
        p_h1h, p_fc2T, out, 256, 0,
        fc2_b, x, nullptr, nullptr, nullptr, nullptr);
}

// round 17
// speedup vs baseline: 1.0799x; 1.0799x over previous
#include <cuda_runtime.h>
#include <cuda_fp16.h>
#include <cstdint>
#include <math.h>

#define DIM     256
#define HEADS   8
#define HDIM    32
#define GW      64
#define HW      56
#define NPIX    3136            // 56*56
#define BATCH   16
#define NTOK    (BATCH * NPIX)  // 50176
#define HIDDEN  1024
#define LN_EPS  1e-6f
#define BN_EPS  1e-3f
#define L2_EPS  1e-12f
#define SCALE_Q 0.17677669529663689f  // 32^-0.5
#define NSPLIT  14                     // 3136 = 14 * 224

// ---------------- scratch (static device globals; no cudaMalloc) -------------
__device__ __align__(16) float  d_dwconv   [NTOK * DIM];
__device__ __align__(16) __half d_norm1h   [NTOK * DIM];
__device__ __align__(16) __half d_qTh      [BATCH * HEADS * HDIM * NPIX]; // [b][h][d][n]
__device__ __align__(16) __half d_kTh      [BATCH * HEADS * HDIM * NPIX];
__device__ __align__(16) __half d_vh       [NTOK * DIM];
__device__ __align__(16) float  d_attn_part[NSPLIT * BATCH * HEADS * HDIM * HDIM];
__device__ __align__(16) __half d_wbTh     [BATCH * DIM * DIM];   // [b][c][h*32+d]
__device__ __align__(16) __half d_mergedh  [NTOK * DIM];
__device__ __align__(16) __half d_h1h      [NTOK * HIDDEN];
__device__ __align__(16) __half d_qkvTh    [768 * 256];
__device__ __align__(16) __half d_fc1T     [1024 * 256];
__device__ __align__(16) __half d_fc2T     [256 * 1024];

// ---------------- PTX helpers -------------------------------------------------
__device__ __forceinline__ void cp_async16_s(uint32_t saddr, const void* gptr) {
    asm volatile("cp.async.cg.shared.global [%0], [%1], 16;\n" :: "r"(saddr), "l"(gptr));
}
__device__ __forceinline__ void cp_commit() { asm volatile("cp.async.commit_group;\n"); }

__device__ __forceinline__ void ldsm_x4(uint32_t r[4], uint32_t addr) {
    asm volatile("ldmatrix.sync.aligned.m8n8.x4.shared.b16 {%0,%1,%2,%3}, [%4];"
        : "=r"(r[0]), "=r"(r[1]), "=r"(r[2]), "=r"(r[3]) : "r"(addr));
}
__device__ __forceinline__ void mma_f16(float c[4], const uint32_t a[4],
                                        uint32_t b0, uint32_t b1) {
    asm volatile(
        "mma.sync.aligned.m16n8k16.row.col.f32.f16.f16.f32 "
        "{%0,%1,%2,%3}, {%4,%5,%6,%7}, {%8,%9}, {%0,%1,%2,%3};"
        : "+f"(c[0]), "+f"(c[1]), "+f"(c[2]), "+f"(c[3])
        : "r"(a[0]), "r"(a[1]), "r"(a[2]), "r"(a[3]), "r"(b0), "r"(b1));
}

// ------- kernel 0: transpose weights -> fp16 [N, K] ---------------------------
__global__ void __launch_bounds__(256) transpose3_kernel(
    const float* __restrict__ qkv_w, const float* __restrict__ fc1_w,
    const float* __restrict__ fc2_w)
{
    const float* src; __half* dst; int R, C;
    if (blockIdx.z == 0)      { src = qkv_w; dst = d_qkvTh; R = 256;  C = 768;  }
    else if (blockIdx.z == 1) { src = fc1_w; dst = d_fc1T;  R = 256;  C = 1024; }
    else                      { src = fc2_w; dst = d_fc2T;  R = 1024; C = 256;  }
    int x0 = blockIdx.x * 32, y0 = blockIdx.y * 32;
    if (x0 >= C || y0 >= R) return;

    __shared__ float t[32][33];
    int tx = threadIdx.x & 31, ty = threadIdx.x >> 5;
    #pragma unroll
    for (int i = ty; i < 32; i += 8)
        t[i][tx] = src[(size_t)(y0 + i) * C + x0 + tx];
    __syncthreads();
    #pragma unroll
    for (int i = ty; i < 32; i += 8)
        dst[(size_t)(x0 + i) * R + y0 + tx] = __float2half(t[tx][i]);
}

// ---- kernel 1: dwconv3x3 + group cumsum + LayerNorm, warp-per-pixel-PAIR ----
// Each warp handles 2 adjacent pixels (even-aligned, same image row since
// HW=56 is even). Neighbor columns ww-1..ww+2 loaded once, shared by the pair;
// out-of-range cells zero-filled (adding +/-0 is value-identical to skipping).
__global__ void __launch_bounds__(256) dwln_kernel(
    const float* __restrict__ x, const float* __restrict__ dwk,
    const float* __restrict__ dwb, const float* __restrict__ g,
    const float* __restrict__ be)
{
    const int lane = threadIdx.x & 31;
    const int wrp  = threadIdx.x >> 5;
    const int pix0 = blockIdx.x * 16 + wrp * 2;   // even => pair shares a row
    const int b  = pix0 / NPIX;
    const int p0 = pix0 - b * NPIX;
    const int hh = p0 / HW, ww = p0 - hh * HW;    // ww even, ww+1 < HW
    const int c  = lane * 8;

    float v0[8], v1[8];
    if (lane < 8) {
        float4 a0 = *(const float4*)&x[(size_t)pix0 * DIM + c];
        float4 a1 = *(const float4*)&x[(size_t)pix0 * DIM + c + 4];
        v0[0]=a0.x; v0[1]=a0.y; v0[2]=a0.z; v0[3]=a0.w;
        v0[4]=a1.x; v0[5]=a1.y; v0[6]=a1.z; v0[7]=a1.w;
        float4 c0 = *(const float4*)&x[(size_t)(pix0 + 1) * DIM + c];
        float4 c1 = *(const float4*)&x[(size_t)(pix0 + 1) * DIM + c + 4];
        v1[0]=c0.x; v1[1]=c0.y; v1[2]=c0.z; v1[3]=c0.w;
        v1[4]=c1.x; v1[5]=c1.y; v1[6]=c1.z; v1[7]=c1.w;
    } else {
        const int cc = c - GW;                    // 0..184
        float4 bb0 = *(const float4*)&dwb[cc];
        float4 bb1 = *(const float4*)&dwb[cc + 4];
        v0[0]=bb0.x; v0[1]=bb0.y; v0[2]=bb0.z; v0[3]=bb0.w;
        v0[4]=bb1.x; v0[5]=bb1.y; v0[6]=bb1.z; v0[7]=bb1.w;
        #pragma unroll
        for (int i = 0; i < 8; i++) v1[i] = v0[i];

        #pragma unroll
        for (int ky = 0; ky < 3; ky++) {
            int hy = hh + ky - 1;
            bool rok = (unsigned)hy < (unsigned)HW;
            float4 cx[4][2];
            #pragma unroll
            for (int ci = 0; ci < 4; ci++) {
                int wx = ww - 1 + ci;
                if (rok && (unsigned)wx < (unsigned)HW) {
                    const float* xp = &x[((size_t)(b * HW + hy) * HW + wx) * DIM + c];
                    cx[ci][0] = *(const float4*)xp;
                    cx[ci][1] = *(const float4*)(xp + 4);
                } else {
                    cx[ci][0] = make_float4(0.f, 0.f, 0.f, 0.f);
                    cx[ci][1] = make_float4(0.f, 0.f, 0.f, 0.f);
                }
            }
            #pragma unroll
            for (int kx = 0; kx < 3; kx++) {
                const float* wp = &dwk[(ky * 3 + kx) * 192 + cc];
                float4 w0 = *(const float4*)wp, w1 = *(const float4*)(wp + 4);
                v0[0] += cx[kx][0].x * w0.x;     v0[1] += cx[kx][0].y * w0.y;
                v0[2] += cx[kx][0].z * w0.z;     v0[3] += cx[kx][0].w * w0.w;
                v0[4] += cx[kx][1].x * w1.x;     v0[5] += cx[kx][1].y * w1.y;
                v0[6] += cx[kx][1].z * w1.z;     v0[7] += cx[kx][1].w * w1.w;
                v1[0] += cx[kx + 1][0].x * w0.x; v1[1] += cx[kx + 1][0].y * w0.y;
                v1[2] += cx[kx + 1][0].z * w0.z; v1[3] += cx[kx + 1][0].w * w0.w;
                v1[4] += cx[kx + 1][1].x * w1.x; v1[5] += cx[kx + 1][1].y * w1.y;
                v1[6] += cx[kx + 1][1].z * w1.z; v1[7] += cx[kx + 1][1].w * w1.w;
            }
        }
    }

    // group cumsum for both pixels
    {
        const int s0 = 8 + (lane & 7);
        const int gi = (lane >> 3) - 1;
        #pragma unroll
        for (int i = 0; i < 8; i++) {
            float k0 = __shfl_sync(0xffffffffu, v0[i], s0);
            float k1 = __shfl_sync(0xffffffffu, v0[i], s0 + 8);
            float k2 = __shfl_sync(0xffffffffu, v0[i], s0 + 16);
            if (lane >= 8) {
                float s = k0;
                if (gi >= 1) s += k1;
                if (gi >= 2) s += k2;
                v0[i] = s;
            }
            k0 = __shfl_sync(0xffffffffu, v1[i], s0);
            k1 = __shfl_sync(0xffffffffu, v1[i], s0 + 8);
            k2 = __shfl_sync(0xffffffffu, v1[i], s0 + 16);
            if (lane >= 8) {
                float s = k0;
                if (gi >= 1) s += k1;
                if (gi >= 2) s += k2;
                v1[i] = s;
            }
        }
    }

    float4 g0 = *(const float4*)&g[c],  g1 = *(const float4*)&g[c + 4];
    float4 e0 = *(const float4*)&be[c], e1 = *(const float4*)&be[c + 4];

    #pragma unroll
    for (int px = 0; px < 2; px++) {
        float* val = (px == 0) ? v0 : v1;
        const int pix = pix0 + px;

        float sum = 0.f;
        #pragma unroll
        for (int i = 0; i < 8; i++) sum += val[i];
        #pragma unroll
        for (int o = 16; o; o >>= 1) sum += __shfl_xor_sync(0xffffffffu, sum, o);
        float mean = sum * (1.0f / 256.0f);

        float ss = 0.f;
        #pragma unroll
        for (int i = 0; i < 8; i++) { float d = val[i] - mean; ss += d * d; }
        #pragma unroll
        for (int o = 16; o; o >>= 1) ss += __shfl_xor_sync(0xffffffffu, ss, o);
        float rstd = rsqrtf(ss * (1.0f / 256.0f) + LN_EPS);

        *(float4*)&d_dwconv[(size_t)pix * DIM + c]     = make_float4(val[0], val[1], val[2], val[3]);
        *(float4*)&d_dwconv[(size_t)pix * DIM + c + 4] = make_float4(val[4], val[5], val[6], val[7]);

        float n[8];
        n[0]=(val[0]-mean)*rstd*g0.x+e0.x; n[1]=(val[1]-mean)*rstd*g0.y+e0.y;
        n[2]=(val[2]-mean)*rstd*g0.z+e0.z; n[3]=(val[3]-mean)*rstd*g0.w+e0.w;
        n[4]=(val[4]-mean)*rstd*g1.x+e1.x; n[5]=(val[5]-mean)*rstd*g1.y+e1.y;
        n[6]=(val[6]-mean)*rstd*g1.z+e1.z; n[7]=(val[7]-mean)*rstd*g1.w+e1.w;
        __half2 h0 = __floats2half2_rn(n[0], n[1]);
        __half2 h1 = __floats2half2_rn(n[2], n[3]);
        __half2 h2 = __floats2half2_rn(n[4], n[5]);
        __half2 h3 = __floats2half2_rn(n[6], n[7]);
        uint4 u;
        u.x = *(uint32_t*)&h0; u.y = *(uint32_t*)&h1;
        u.z = *(uint32_t*)&h2; u.w = *(uint32_t*)&h3;
        *(uint4*)&d_norm1h[(size_t)pix * DIM + c] = u;
    }
}

// -------- fp16 GEMM v2: BK=64 halves (128B rows), 3-stage single-barrier ------
// MODE 1: BN( +bias +add1 fp32 ) -> half (proj, PERBATCH)
// MODE 2: gelu(+bias) -> half (fc1)     MODE 3: +bias +add1 -> float (fc2)
// MODE 4: qkv: per-head l2norm; qTh/kTh fp16 transposed (smem-staged), vh dense
#define HG_BOFF  49152
#define HG_SMEM  98304

template<int KDIM, int MODE, bool PERBATCH>
__global__ void __launch_bounds__(256, 2)
hgemm(const __half* __restrict__ A,
      const __half* __restrict__ Bt,
      void* __restrict__ Cv, int ldc, int m_off,
      const float* __restrict__ bias, const float* __restrict__ add1,
      const float* __restrict__ bn_g, const float* __restrict__ bn_b,
      const float* __restrict__ bn_m, const float* __restrict__ bn_v)
{
    extern __shared__ char smem[];
    const uint32_t sb = (uint32_t)__cvta_generic_to_shared(smem);
    const int tid  = threadIdx.x;
    const int lane = tid & 31;
    const int w    = tid >> 5;
    const int wm   = w >> 2;
    const int wn   = w & 3;

    int m0, mrows;
    if (PERBATCH) {
        int batch = blockIdx.y / 25;
        int bt    = blockIdx.y % 25;
        m0 = batch * NPIX + bt * 128;
        mrows = min(128, NPIX - bt * 128);
    } else {
        m0 = m_off + blockIdx.y * 128; mrows = 128;
    }
    const int n0 = blockIdx.x * 128;
    const __half* Bp = PERBATCH ? (Bt + (size_t)(blockIdx.y / 25) * 65536) : Bt;

    float acc[4][4][4];
    #pragma unroll
    for (int mi = 0; mi < 4; mi++)
        #pragma unroll
        for (int ni = 0; ni < 4; ni++)
            #pragma unroll
            for (int q = 0; q < 4; q++) acc[mi][ni][q] = 0.f;

    auto load_stage = [&](int st) {
        int slot = st % 3;
        int k0 = st * 64;                 // halves
        #pragma unroll
        for (int i = 0; i < 4; i++) {
            int lin = tid + 256 * i;      // 0..1023
            int r = lin >> 3, ch = lin & 7;
            int rg = m0 + (r < mrows ? r : mrows - 1);
            cp_async16_s(sb + slot * 16384 + r * 128 + ((ch ^ (r & 7)) << 4),
                         A + (size_t)rg * KDIM + k0 + ch * 8);
        }
        #pragma unroll
        for (int i = 0; i < 4; i++) {
            int lin = tid + 256 * i;
            int r = lin >> 3, ch = lin & 7;
            cp_async16_s(sb + HG_BOFF + slot * 16384 + r * 128 + ((ch ^ (r & 7)) << 4),
                         Bp + (size_t)(n0 + r) * KDIM + k0 + ch * 8);
        }
        cp_commit();
    };

    const int KT = KDIM / 64;
    load_stage(0); load_stage(1);

    const int sx    = lane & 7;
    const int arow  = lane & 15;
    const int akoff = lane >> 4;
    const int brow  = ((lane >> 4) << 3) + (lane & 7);
    const int bkoff = (lane >> 3) & 1;

    for (int s = 0; s < KT; s++) {
        int slot = s % 3;
        if (s < KT - 1) asm volatile("cp.async.wait_group 1;\n" ::: "memory");
        else            asm volatile("cp.async.wait_group 0;\n" ::: "memory");
        __syncthreads();
        if (s + 2 < KT) load_stage(s + 2);

        uint32_t aBase = sb + slot * 16384 + (wm * 64) * 128;
        uint32_t bBase = sb + HG_BOFF + slot * 16384 + (wn * 32) * 128;

        #pragma unroll
        for (int ks = 0; ks < 4; ks++) {
            uint32_t a[4][4];
            #pragma unroll
            for (int mi = 0; mi < 4; mi++)
                ldsm_x4(a[mi], aBase + (mi * 16 + arow) * 128
                               + (((2 * ks + akoff) ^ sx) << 4));
            uint32_t bf[2][4];
            #pragma unroll
            for (int nj = 0; nj < 2; nj++)
                ldsm_x4(bf[nj], bBase + (nj * 16 + brow) * 128
                                + (((2 * ks + bkoff) ^ sx) << 4));
            #pragma unroll
            for (int mi = 0; mi < 4; mi++)
                #pragma unroll
                for (int ni = 0; ni < 4; ni++)
                    mma_f16(acc[mi][ni], a[mi],
                            bf[ni >> 1][(ni & 1) * 2], bf[ni >> 1][(ni & 1) * 2 + 1]);
        }
    }

    // ---- MODE 4 q/k path: l2norm + smem-staged transposed fp16 store ----
    if (MODE == 4 && n0 < 512) {
        float* sT = (float*)smem;             // [col 128][row 128], stride 132
        __syncthreads();
        #pragma unroll
        for (int mi = 0; mi < 4; mi++) {
            #pragma unroll
            for (int h = 0; h < 2; h++) {
                float ss = 0.f;
                #pragma unroll
                for (int ni = 0; ni < 4; ni++) {
                    float v0 = acc[mi][ni][2 * h], v1 = acc[mi][ni][2 * h + 1];
                    ss += v0 * v0 + v1 * v1;
                }
                ss += __shfl_xor_sync(0xffffffffu, ss, 1);
                ss += __shfl_xor_sync(0xffffffffu, ss, 2);
                float sc = rsqrtf(fmaxf(ss, L2_EPS));
                if (n0 < 256) sc *= SCALE_Q;

                int rowl = wm * 64 + mi * 16 + (lane >> 2) + h * 8;
                #pragma unroll
                for (int ni = 0; ni < 4; ni++) {
                    int dl = wn * 32 + ni * 8 + (lane & 3) * 2;
                    sT[dl * 132 + rowl]       = acc[mi][ni][2 * h] * sc;
                    sT[(dl + 1) * 132 + rowl] = acc[mi][ni][2 * h + 1] * sc;
                }
            }
        }
        __syncthreads();
        __half* dstT = (n0 < 256) ? d_qTh : d_kTh;
        #pragma unroll
        for (int i = 0; i < 8; i++) {
            int idx = tid + i * 256;          // 0..2047
            int cl  = idx >> 4;               // 0..127
            int row = (idx & 15) * 8;         // 0..120
            int grow = m0 + row;
            int bb = grow / NPIX;
            int n  = grow - bb * NPIX;        // 8-run never straddles batch (3136%8==0)
            int gcol = n0 + cl;
            int head = (gcol & 255) >> 5;
            int d    = gcol & 31;
            float4 v4a = *(float4*)&sT[cl * 132 + row];
            float4 v4b = *(float4*)&sT[cl * 132 + row + 4];
            __half2 p0 = __floats2half2_rn(v4a.x, v4a.y);
            __half2 p1 = __floats2half2_rn(v4a.z, v4a.w);
            __half2 p2 = __floats2half2_rn(v4b.x, v4b.y);
            __half2 p3 = __floats2half2_rn(v4b.z, v4b.w);
            uint4 u;
            u.x = *(uint32_t*)&p0; u.y = *(uint32_t*)&p1;
            u.z = *(uint32_t*)&p2; u.w = *(uint32_t*)&p3;
            *(uint4*)&dstT[((size_t)(bb * 8 + head) * 32 + d) * NPIX + n] = u;
        }
        return;
    }

    // ---- epilogue ----
    #pragma unroll
    for (int mi = 0; mi < 4; mi++) {
        #pragma unroll
        for (int h = 0; h < 2; h++) {
            int lr = wm * 64 + mi * 16 + (lane >> 2) + h * 8;
            if (PERBATCH && lr >= mrows) continue;
            size_t grow = (size_t)(m0 + lr);
            #pragma unroll
            for (int ni = 0; ni < 4; ni++) {
                float v0 = acc[mi][ni][2 * h], v1 = acc[mi][ni][2 * h + 1];
                if (MODE == 4) {
                    // v block (n0 >= 512): fp16 dense store, ldc = 256
                    int gc = (n0 - 512) + wn * 32 + ni * 8 + (lane & 3) * 2;
                    *(__half2*)((__half*)Cv + grow * ldc + gc) = __floats2half2_rn(v0, v1);
                    continue;
                }
                int gc = n0 + wn * 32 + ni * 8 + (lane & 3) * 2;
                if (MODE == 1) {
                    float2 ad = *(const float2*)&add1[grow * 256 + gc];
                    v0 += bias[gc]     + ad.x;
                    v1 += bias[gc + 1] + ad.y;
                    v0 = (v0 - bn_m[gc    ]) * rsqrtf(bn_v[gc    ] + BN_EPS) * bn_g[gc    ] + bn_b[gc    ];
                    v1 = (v1 - bn_m[gc + 1]) * rsqrtf(bn_v[gc + 1] + BN_EPS) * bn_g[gc + 1] + bn_b[gc + 1];
                    *(__half2*)((__half*)Cv + grow * ldc + gc) = __floats2half2_rn(v0, v1);
                } else if (MODE == 2) {
                    v0 += bias[gc];   v1 += bias[gc + 1];
                    v0 = 0.5f * v0 * (1.0f + erff(v0 * 0.70710678118654752f));
                    v1 = 0.5f * v1 * (1.0f + erff(v1 * 0.70710678118654752f));
                    *(__half2*)((__half*)Cv + grow * ldc + gc) = __floats2half2_rn(v0, v1);
                } else {
                    float2 ad = *(const float2*)&add1[grow * 256 + gc];
                    v0 += bias[gc]     + ad.x;
                    v1 += bias[gc + 1] + ad.y;
                    *(float2*)&((float*)Cv)[grow * ldc + gc] = make_float2(v0, v1);
                }
            }
        }
    }
}

// ------- attn split-K (fp16 mma): per (b,h,split) partial 32x32 q^T k --------
#define AS_STAGE 5120
#define AS_SMEM  15360

__global__ void __launch_bounds__(256) attn_split_kernel()
{
    extern __shared__ char smem[];
    const uint32_t sb = (uint32_t)__cvta_generic_to_shared(smem);
    const int bh = blockIdx.x;
    const int split = blockIdx.y;
    const int tid = threadIdx.x, lane = tid & 31, w = tid >> 5;
    const int wm = w >> 2, wn = w & 3;

    const __half* qT = d_qTh + (size_t)bh * 32 * NPIX + split * 224;
    const __half* kT = d_kTh + (size_t)bh * 32 * NPIX + split * 224;

    float c[4] = {0.f, 0.f, 0.f, 0.f};

    auto load_stage = [&](int st) {
        int slot = st % 3;
        int k0 = st * 32;                     // halves
        int op = tid >> 7;                    // 0 = q, 1 = k
        int rr = (tid >> 2) & 31;
        int ch = tid & 3;
        const __half* src = (op ? kT : qT) + (size_t)rr * NPIX + k0 + ch * 8;
        cp_async16_s(sb + slot * AS_STAGE + op * 2560 + rr * 80 + ch * 16, src);
        cp_commit();
    };

    const int KT = 7;                         // 224 / 32
    load_stage(0); load_stage(1);

    const int nj   = wn >> 1;
    const int nsel = (wn & 1) * 2;

    for (int s = 0; s < KT; s++) {
        int slot = s % 3;
        if (s < KT - 1) asm volatile("cp.async.wait_group 1;\n" ::: "memory");
        else            asm volatile("cp.async.wait_group 0;\n" ::: "memory");
        __syncthreads();
        if (s + 2 < KT) load_stage(s + 2);

        uint32_t aBase = sb + slot * AS_STAGE + (wm * 16) * 80;
        uint32_t bBase = sb + slot * AS_STAGE + 2560;
        #pragma unroll
        for (int ks = 0; ks < 2; ks++) {
            const int kc = ks * 2;
            uint32_t a[4], bf[4];
            ldsm_x4(a, aBase + (lane & 15) * 80 + (kc + (lane >> 4)) * 16);
            ldsm_x4(bf, bBase + (nj * 16 + ((lane >> 4) << 3) + (lane & 7)) * 80
                        + (kc + ((lane >> 3) & 1)) * 16);
            mma_f16(c, a, bf[nsel], bf[nsel + 1]);
        }
    }

    float* dst = d_attn_part + ((size_t)split * 128 + bh) * 1024;
    int row = wm * 16 + (lane >> 2);
    int col = wn * 8 + (lane & 3) * 2;
    dst[row * 32 + col]           = c[0];
    dst[row * 32 + col + 1]       = c[1];
    dst[(row + 8) * 32 + col]     = c[2];
    dst[(row + 8) * 32 + col + 1] = c[3];
}

// ------- attn finalize + softmax + wbT^h = (blockdiag attn @ proj_w)^T -------
__global__ void __launch_bounds__(1024) attn_wb_kernel(const float* __restrict__ proj_w)
{
    int bh = blockIdx.x;
    int b = bh >> 3, h = bh & 7;
    int tid = threadIdx.x;
    int e = tid & 31, d = tid >> 5;

    __shared__ float sA[32][33];
    __shared__ float sW[32][256];

    float acc = 0.f;
    #pragma unroll
    for (int s = 0; s < NSPLIT; s++)
        acc += d_attn_part[((size_t)s * 128 + bh) * 1024 + d * 32 + e];

    float m = acc;
    #pragma unroll
    for (int o = 16; o; o >>= 1) m = fmaxf(m, __shfl_xor_sync(0xffffffffu, m, o));
    float ex = expf(acc - m);
    float sum = ex;
    #pragma unroll
    for (int o = 16; o; o >>= 1) sum += __shfl_xor_sync(0xffffffffu, sum, o);
    sA[d][e] = ex / sum;

    #pragma unroll
    for (int idx = tid; idx < 8192; idx += 1024)
        sW[idx >> 8][idx & 255] = proj_w[(h * 32 + (idx >> 8)) * 256 + (idx & 255)];
    __syncthreads();

    #pragma unroll
    for (int idx = tid; idx < 8192; idx += 1024) {
        int d2 = idx & 31, c = idx >> 5;
        float s = 0.f;
        #pragma unroll
        for (int ee = 0; ee < 32; ee++) s += sA[d2][ee] * sW[ee][c];
        d_wbTh[(size_t)b * 65536 + c * 256 + h * 32 + d2] = __float2half(s);
    }
}

// ---------------- launch ------------------------------------------------------
extern "C" void kernel_launch(void* const* d_in, const int* in_sizes, int n_in,
                              void* d_out, int out_size)
{
    const float* x        = (const float*)d_in[0];
    const float* dw_kernel= (const float*)d_in[1];
    const float* dw_bias  = (const float*)d_in[2];
    const float* ln_gamma = (const float*)d_in[3];
    const float* ln_beta  = (const float*)d_in[4];
    const float* qkv_w    = (const float*)d_in[5];
    const float* proj_w   = (const float*)d_in[6];
    const float* proj_b   = (const float*)d_in[7];
    const float* bn_gamma = (const float*)d_in[8];
    const float* bn_beta  = (const float*)d_in[9];
    const float* bn_mean  = (const float*)d_in[10];
    const float* bn_var   = (const float*)d_in[11];
    const float* fc1_w    = (const float*)d_in[12];
    const float* fc1_b    = (const float*)d_in[13];
    const float* fc2_w    = (const float*)d_in[14];
    const float* fc2_b    = (const float*)d_in[15];
    float* out = (float*)d_out;

    float  *p_dwconv;
    __half *p_norm1h, *p_vh, *p_wbTh, *p_mergedh, *p_h1h, *p_qkvTh, *p_fc1T, *p_fc2T;
    cudaGetSymbolAddress((void**)&p_dwconv,  d_dwconv);
    cudaGetSymbolAddress((void**)&p_norm1h,  d_norm1h);
    cudaGetSymbolAddress((void**)&p_vh,      d_vh);
    cudaGetSymbolAddress((void**)&p_wbTh,    d_wbTh);
    cudaGetSymbolAddress((void**)&p_mergedh, d_mergedh);
    cudaGetSymbolAddress((void**)&p_h1h,     d_h1h);
    cudaGetSymbolAddress((void**)&p_qkvTh,   d_qkvTh);
    cudaGetSymbolAddress((void**)&p_fc1T,    d_fc1T);
    cudaGetSymbolAddress((void**)&p_fc2T,    d_fc2T);

    cudaFuncSetAttribute(hgemm<256, 4, false>,
                         cudaFuncAttributeMaxDynamicSharedMemorySize, HG_SMEM);
    cudaFuncSetAttribute(hgemm<256, 1, true>,
                         cudaFuncAttributeMaxDynamicSharedMemorySize, HG_SMEM);
    cudaFuncSetAttribute(hgemm<256, 2, false>,
                         cudaFuncAttributeMaxDynamicSharedMemorySize, HG_SMEM);
    cudaFuncSetAttribute(hgemm<1024, 3, false>,
                         cudaFuncAttributeMaxDynamicSharedMemorySize, HG_SMEM);

    // 1) transpose weights (all fp16)
    transpose3_kernel<<<dim3(32, 32, 3), 256>>>(qkv_w, fc1_w, fc2_w);

    // 2) dwconv + cumsum + LN (warp-per-pixel-pair)
    dwln_kernel<<<NTOK / 16, 256>>>(x, dw_kernel, dw_bias, ln_gamma, ln_beta);

    // 3) qkv GEMM (fp16, BK=64), single launch; qTh/kTh/vh fp16 outputs
    hgemm<256, 4, false><<<dim3(6, 392), 256, HG_SMEM>>>(
        p_norm1h, p_qkvTh, p_vh, 256, 0,
        nullptr, nullptr, nullptr, nullptr, nullptr, nullptr);

    // 4) attn partials (fp16 mma, split-K x14)
    attn_split_kernel<<<dim3(BATCH * HEADS, NSPLIT), 256, AS_SMEM>>>();

    // 5) softmax + wbT (fp16)
    attn_wb_kernel<<<BATCH * HEADS, 1024>>>(proj_w);

    // 6) merged = BN( v @ W_b + proj_b + dwconv ) -> fp16   (fp16 GEMM, per-batch)
    hgemm<256, 1, true><<<dim3(2, BATCH * 25), 256, HG_SMEM>>>(
        p_vh, p_wbTh, p_mergedh, 256, 0,
        proj_b, p_dwconv, bn_gamma, bn_beta, bn_mean, bn_var);

    // 7) h1 = gelu(merged @ fc1_w + fc1_b) -> fp16
    hgemm<256, 2, false><<<dim3(8, NTOK / 128), 256, HG_SMEM>>>(
        p_mergedh, p_fc1T, p_h1h, 1024, 0,
        fc1_b, nullptr, nullptr, nullptr, nullptr, nullptr);

    // 8) out = h1 @ fc2_w + fc2_b + x -> fp32
    hgemm<1024, 3, false><<<dim3(2, NTOK / 128), 256, HG_SMEM>>>(
        p_h1h, p_fc2T, out, 256, 0,
        fc2_b, x, nullptr, nullptr, nullptr, nullptr);
}